// round 15
// baseline (speedup 1.0000x reference)
#include <cuda_runtime.h>
#include <cuda_fp16.h>
#include <cstdint>
#include <math.h>

#define N_NODES 10000
#define N_EDGES 320000
#define N_GRAPHS 64
#define HID 256
#define ELL_CAP 128
#define FILL_BLOCKS 1250           // 1250*256 = 320000 edges
#define EMBED_BLOCKS 10000         // N_NODES*HID/256
#define PACK_BLOCKS 256            // 4 matrices * 65536 halves / (256 thr * 4)

// ---------------- scratch (static __device__, no allocation) ----------------
__device__ __align__(16) float   g_h  [N_NODES * HID];
__device__ __align__(16) __half2 g_t2h[N_NODES * HID / 2];
__device__ __align__(16) __half  g_wph[4 * 256 * 256];   // fp16 weights, k-major [m][k][n]
__device__ int g_cur[N_NODES];          // zero at module load; re-zeroed by pool tail
__device__ __align__(16) int g_ell[N_NODES * ELL_CAP];

__device__ __forceinline__ float silu(float v) {
    return v / (1.0f + expf(-v));
}

__device__ __forceinline__ int clampi(int v, int hi) {
    return v < 0 ? 0 : (v >= hi ? hi - 1 : v);
}

__device__ __forceinline__ void mma_f16(float* d, const unsigned* a, const unsigned* b) {
    asm volatile(
        "mma.sync.aligned.m16n8k16.row.col.f32.f16.f16.f32 "
        "{%0,%1,%2,%3}, {%4,%5,%6,%7}, {%8,%9}, {%0,%1,%2,%3};"
        : "+f"(d[0]), "+f"(d[1]), "+f"(d[2]), "+f"(d[3])
        : "r"(a[0]), "r"(a[1]), "r"(a[2]), "r"(a[3]),
          "r"(b[0]), "r"(b[1]));
}

__device__ __forceinline__ void ldsm_x4(unsigned* r, uint32_t addr) {
    asm volatile("ldmatrix.sync.aligned.m8n8.x4.shared.b16 {%0,%1,%2,%3}, [%4];"
                 : "=r"(r[0]), "=r"(r[1]), "=r"(r[2]), "=r"(r[3]) : "r"(addr));
}

__device__ __forceinline__ void ldsm_x4_trans(unsigned* r, uint32_t addr) {
    asm volatile("ldmatrix.sync.aligned.m8n8.x4.trans.shared.b16 {%0,%1,%2,%3}, [%4];"
                 : "=r"(r[0]), "=r"(r[1]), "=r"(r[2]), "=r"(r[3]) : "r"(addr));
}

__device__ __forceinline__ void cp16(void* smem_dst, const void* gsrc) {
    unsigned s = (unsigned)__cvta_generic_to_shared(smem_dst);
    asm volatile("cp.async.ca.shared.global [%0], [%1], 16;"
                 :: "r"(s), "l"(gsrc));
}

// --- fused setup: ELL fill + embed + W half-pack (one grid, three ranges) ---
__global__ void setup_kernel(const float* __restrict__ x,
                             const float* __restrict__ w,
                             const float* __restrict__ b,
                             const int* __restrict__ src,
                             const int* __restrict__ dst,
                             const float* __restrict__ W1a,
                             const float* __restrict__ W1b,
                             const float* __restrict__ W2a,
                             const float* __restrict__ W2b) {
    int blk = blockIdx.x;
    if (blk < FILL_BLOCKS) {
        int e = blk * 256 + threadIdx.x;
        if (e < N_EDGES) {
            int d = clampi(dst[e], N_NODES);
            int slot = atomicAdd(&g_cur[d], 1);
            if (slot < ELL_CAP)
                g_ell[d * ELL_CAP + slot] = clampi(src[e], N_NODES);
        }
    } else if (blk < FILL_BLOCKS + EMBED_BLOCKS) {
        int idx = (blk - FILL_BLOCKS) * 256 + threadIdx.x;
        if (idx < N_NODES * HID) {
            int n = idx >> 8;
            int d = idx & 255;
            g_h[idx] = silu(x[n] * w[d] + b[d]);
        }
    } else {
        int t = (blk - FILL_BLOCKS - EMBED_BLOCKS) * 256 + threadIdx.x;  // 0..65535
        int m   = t >> 14;                 // matrix 0..3
        int off = (t & 16383) * 4;         // element offset (W is [k][n] row-major)
        const float* Wm = (m == 0) ? W1a : (m == 1) ? W1b : (m == 2) ? W2a : W2b;
        float4 v = *(const float4*)(Wm + off);
        __half2* d2 = (__half2*)(g_wph + m * 65536 + off);
        d2[0] = __floats2half2_rn(v.x, v.y);
        d2[1] = __floats2half2_rn(v.z, v.w);
    }
}

// ---------------- fused conv: t2h = (relu(h@Wa+ba))@Wb + bb -----------------
// Block: 32 rows x full 256 cols, 256 threads (8 warps; warp = 16x64).
// 3 CTAs/SM target; grid 313 single wave. ldmatrix frags; cp.async W stream.
#define FBM 32
#define FAS16 264                  // b16 per As row (256 + 8)
#define FBS16 264                  // b16 per Bs row
#define FA_B16 (FBM * FAS16)       // 8448 halves
#define FB_B16 (32 * FBS16)        // 8448 halves per buffer
#define FUSED_SMEM ((FA_B16 + 2 * FB_B16) * 2)   // 50688 bytes

// B tile kt: 32 k-rows x 256 halves; 1024 16B chunks / 256 threads
__device__ __forceinline__ void cpB(__half* dst, const __half* __restrict__ Wp,
                                    int kt, int tid) {
#pragma unroll
    for (int i = 0; i < 4; i++) {
        int l = tid + 256 * i;          // 0..1023
        int r  = l >> 5;                // k row 0..31
        int c8 = (l & 31) * 8;          // half col 0..248
        cp16(&dst[r * FBS16 + c8], Wp + (size_t)(kt * 32 + r) * 256 + c8);
    }
}

__global__ void __launch_bounds__(256, 3)
conv_fused(const float* __restrict__ A,
           const __half* __restrict__ Wa, const float* __restrict__ ba,
           const __half* __restrict__ Wb, const float* __restrict__ bb,
           __half2* __restrict__ out, int M) {
    extern __shared__ __half sm16[];
    __half* As = sm16;                     // 32 x 264 (A tile, then C1)
    __half* Bs = sm16 + FA_B16;            // 2 x 32 x 264

    int tid = threadIdx.x, lane = tid & 31, w = tid >> 5;
    int wr = (w & 1) * 16;                 // warp row offset (0/16)
    int wc = (w >> 1) * 64;                // warp col offset (0/64/128/192)
    int rowBase = blockIdx.x * FBM;
    int g = lane >> 2, t4 = lane & 3;
    int lr = lane & 7, q = lane >> 3;      // ldmatrix lane groups

    uint32_t as_u = (uint32_t)__cvta_generic_to_shared(As);
    uint32_t bs_u[2];
    bs_u[0] = (uint32_t)__cvta_generic_to_shared(Bs);
    bs_u[1] = bs_u[0] + FB_B16 * 2;

    // ldmatrix base addresses (byte offsets in shared space)
    // A x4 tiles: (m0-7,k0-7),(m8-15,k0-7),(m0-7,k8-15),(m8-15,k8-15)
    uint32_t aA0 = as_u + (uint32_t)(((wr + (q & 1) * 8 + lr) * FAS16 + (q >> 1) * 8) * 2);
    // B (trans) x4 tiles: (k0-7,n0-7),(k8-15,n0-7),(k0-7,n8-15),(k8-15,n8-15)
    uint32_t bOff = (uint32_t)((((q & 1) * 8 + lr) * FBS16 + (q >> 1) * 8) * 2);

    // A tile: fp32 -> half smem (32 rows x 64 float4 = 2048 chunks)
#pragma unroll
    for (int i = 0; i < 8; i++) {
        int l = tid + 256 * i;
        int r = l >> 6, c4 = l & 63;
        int grow = rowBase + r;
        float4 v = make_float4(0.f, 0.f, 0.f, 0.f);
        if (grow < M) v = *(const float4*)(A + (size_t)grow * HID + c4 * 4);
        __half2* row2 = (__half2*)(As + r * FAS16);
        row2[c4 * 2]     = __floats2half2_rn(v.x, v.y);
        row2[c4 * 2 + 1] = __floats2half2_rn(v.z, v.w);
    }

    float acc[8][4];
#pragma unroll
    for (int ni = 0; ni < 8; ni++)
#pragma unroll
        for (int r = 0; r < 4; r++) acc[ni][r] = 0.0f;

#pragma unroll
    for (int stage = 0; stage < 2; stage++) {
        const __half* Wp = (stage == 0) ? Wa : Wb;
        cpB(Bs, Wp, 0, tid);
        asm volatile("cp.async.commit_group;");
        int buf = 0;
#pragma unroll
        for (int kt = 0; kt < 8; kt++) {
            asm volatile("cp.async.wait_group 0;");
            __syncthreads();               // tile kt visible; prior reads of buf^1 done
            if (kt < 7) {
                cpB(Bs + (buf ^ 1) * FB_B16, Wp, kt + 1, tid);
                asm volatile("cp.async.commit_group;");
            }
            // compute tile kt from buf
#pragma unroll
            for (int s = 0; s < 2; s++) {
                uint32_t aoff = (uint32_t)((kt * 32 + s * 16) * 2);
                unsigned a0[4];
                ldsm_x4(a0, aA0 + aoff);
                uint32_t bbase = bs_u[buf] + bOff + (uint32_t)(s * 16 * FBS16 * 2);
#pragma unroll
                for (int nj = 0; nj < 4; nj++) {
                    unsigned b[4];
                    ldsm_x4_trans(b, bbase + (uint32_t)((wc + nj * 16) * 2));
                    mma_f16(acc[nj * 2],     a0, b);
                    mma_f16(acc[nj * 2 + 1], a0, b + 2);
                }
            }
            buf ^= 1;
        }
        __syncthreads();                   // all stage reads done before As overwrite

        if (stage == 0) {
            // epilogue 1: C1 = relu(acc + ba) -> back into As; reset acc
#pragma unroll
            for (int ni = 0; ni < 8; ni++) {
                int col = wc + ni * 8 + t4 * 2;
                float b0 = ba[col], b1 = ba[col + 1];
                float v00 = fmaxf(acc[ni][0] + b0, 0.f);
                float v01 = fmaxf(acc[ni][1] + b1, 0.f);
                float v10 = fmaxf(acc[ni][2] + b0, 0.f);
                float v11 = fmaxf(acc[ni][3] + b1, 0.f);
                int r0 = wr + g;
                ((__half2*)(As + r0 * FAS16))[col >> 1]       = __floats2half2_rn(v00, v01);
                ((__half2*)(As + (r0 + 8) * FAS16))[col >> 1] = __floats2half2_rn(v10, v11);
                acc[ni][0] = acc[ni][1] = acc[ni][2] = acc[ni][3] = 0.0f;
            }
        }
    }

    // epilogue 2: out = acc + bb (half2 global store)
#pragma unroll
    for (int ni = 0; ni < 8; ni++) {
        int col = wc + ni * 8 + t4 * 2;
        float b0 = bb[col], b1 = bb[col + 1];
        int r0 = rowBase + wr + g;
        int r1 = r0 + 8;
        if (r0 < M)
            out[(size_t)r0 * (HID / 2) + (col >> 1)] =
                __floats2half2_rn(acc[ni][0] + b0, acc[ni][1] + b1);
        if (r1 < M)
            out[(size_t)r1 * (HID / 2) + (col >> 1)] =
                __floats2half2_rn(acc[ni][2] + b0, acc[ni][3] + b1);
    }
}

// ------- edge aggregation: warp-per-node float4 gather-max (R7 2-deep) ------
__global__ void agg_kernel() {
    const unsigned FULL = 0xffffffffu;
    int warp = threadIdx.x >> 5;
    int lane = threadIdx.x & 31;
    int n = blockIdx.x * 8 + warp;
    if (n >= N_NODES) return;

    int cnt = min(g_cur[n], ELL_CAP);
    const int* lst = g_ell + n * ELL_CAP;
    const float4* t2v = (const float4*)g_t2h;   // 32 float4 per row

    unsigned ninf = 0xFC00FC00u;
    __half2 mneg = *(__half2*)&ninf;
    __half2 m[8];
#pragma unroll
    for (int q = 0; q < 8; q++) m[q] = mneg;

    for (int base = 0; base < cnt; base += 32) {
        int e = base + lane;
        int idx = (e < cnt) ? lst[e] : 0;
        int c = min(32, cnt - base);
        int j = 0;
        for (; j + 2 <= c; j += 2) {
            int s0 = __shfl_sync(FULL, idx, j);
            int s1 = __shfl_sync(FULL, idx, j + 1);
            float4 v0 = t2v[s0 * 32 + lane];
            float4 v1 = t2v[s1 * 32 + lane];
            m[0] = __hmax2(m[0], *(__half2*)&v0.x);
            m[1] = __hmax2(m[1], *(__half2*)&v0.y);
            m[2] = __hmax2(m[2], *(__half2*)&v0.z);
            m[3] = __hmax2(m[3], *(__half2*)&v0.w);
            m[4] = __hmax2(m[4], *(__half2*)&v1.x);
            m[5] = __hmax2(m[5], *(__half2*)&v1.y);
            m[6] = __hmax2(m[6], *(__half2*)&v1.z);
            m[7] = __hmax2(m[7], *(__half2*)&v1.w);
        }
        if (j < c) {
            int s0 = __shfl_sync(FULL, idx, j);
            float4 v0 = t2v[s0 * 32 + lane];
            m[0] = __hmax2(m[0], *(__half2*)&v0.x);
            m[1] = __hmax2(m[1], *(__half2*)&v0.y);
            m[2] = __hmax2(m[2], *(__half2*)&v0.z);
            m[3] = __hmax2(m[3], *(__half2*)&v0.w);
        }
    }
#pragma unroll
    for (int q = 0; q < 4; q++) m[q] = __hmax2(m[q], m[q + 4]);

    float f[8];
#pragma unroll
    for (int q = 0; q < 4; q++) {
        float2 p = __half22float2(m[q]);
        f[2 * q]     = (cnt > 0) ? p.x : 0.0f;
        f[2 * q + 1] = (cnt > 0) ? p.y : 0.0f;
    }
    float4* hp = (float4*)(g_h + (size_t)n * HID) + lane * 2;
    float4 h0 = hp[0], h1 = hp[1];
    h0.x += silu(f[0]); h0.y += silu(f[1]); h0.z += silu(f[2]); h0.w += silu(f[3]);
    h1.x += silu(f[4]); h1.y += silu(f[5]); h1.z += silu(f[6]); h1.w += silu(f[7]);
    hp[0] = h0; hp[1] = h1;
}

// ------- global mean pool (batch sorted) + re-zero g_cur for next call -----
__global__ void pool_kernel(const int* __restrict__ batch,
                            float* __restrict__ out) {
    int g = blockIdx.x;          // 0..63
    int tid = threadIdx.x;       // 0..255 feature

    int lo = 0, hi = N_NODES;
    while (lo < hi) { int m = (lo + hi) >> 1; if (batch[m] < g) lo = m + 1; else hi = m; }
    int start = lo;
    lo = start; hi = N_NODES;
    while (lo < hi) { int m = (lo + hi) >> 1; if (batch[m] < g + 1) lo = m + 1; else hi = m; }
    int end = lo;

    float s = 0.0f;
    for (int n = start; n < end; n++)
        s += g_h[(size_t)n * HID + tid];
    float c = (float)(end - start);
    out[g * HID + tid] = s / fmaxf(c, 1.0f);

    int z = g * 256 + tid;       // 64*256 = 16384 >= N_NODES
    if (z < N_NODES) g_cur[z] = 0;
}

// ---------------- launch ----------------
extern "C" void kernel_launch(void* const* d_in, const int* in_sizes, int n_in,
                              void* d_out, int out_size) {
    const float* x     = (const float*)d_in[0];
    const int*   ei    = (const int*)d_in[1];
    const int*   batch = (const int*)d_in[2];
    const float* W_emb = (const float*)d_in[3];
    const float* b_emb = (const float*)d_in[4];
    const float* W1a   = (const float*)d_in[5];
    const float* b1a   = (const float*)d_in[6];
    const float* W1b   = (const float*)d_in[7];
    const float* b1b   = (const float*)d_in[8];
    const float* W2a   = (const float*)d_in[9];
    const float* b2a   = (const float*)d_in[10];
    const float* W2b   = (const float*)d_in[11];
    const float* b2b   = (const float*)d_in[12];
    float* out = (float*)d_out;

    const int* src = ei;
    const int* dst = ei + N_EDGES;

    float* h = nullptr; __half2* t2h = nullptr; __half* wph = nullptr;
    cudaGetSymbolAddress((void**)&h,   g_h);
    cudaGetSymbolAddress((void**)&t2h, g_t2h);
    cudaGetSymbolAddress((void**)&wph, g_wph);

    cudaFuncSetAttribute((const void*)conv_fused,
        cudaFuncAttributeMaxDynamicSharedMemorySize, FUSED_SMEM);

    // setup: ELL fill + embed + W pack in one grid
    setup_kernel<<<FILL_BLOCKS + EMBED_BLOCKS + PACK_BLOCKS, 256>>>(
        x, W_emb, b_emb, src, dst, W1a, W1b, W2a, W2b);

    int fgrid = (N_NODES + FBM - 1) / FBM;   // 313

    // conv 1 (fused MLP) + aggregation
    conv_fused<<<fgrid, 256, FUSED_SMEM>>>(h, wph, b1a, wph + 65536, b1b, t2h, N_NODES);
    agg_kernel<<<1250, 256>>>();

    // conv 2
    conv_fused<<<fgrid, 256, FUSED_SMEM>>>(h, wph + 131072, b2a, wph + 196608, b2b, t2h, N_NODES);
    agg_kernel<<<1250, 256>>>();

    // global mean pool (+ g_cur re-zero for next call)
    pool_kernel<<<N_GRAPHS, 256>>>(batch, out);
}

// round 16
// speedup vs baseline: 1.0249x; 1.0249x over previous
#include <cuda_runtime.h>
#include <cuda_fp16.h>
#include <cstdint>
#include <math.h>

#define N_NODES 10000
#define N_EDGES 320000
#define N_GRAPHS 64
#define HID 256
#define ELL_CAP 128
#define FILL_BLOCKS 1250           // 1250*256 = 320000 edges
#define PACK_BLOCKS 256            // 4 matrices * 65536 halves / (256 thr * 4)

// ---------------- scratch (static __device__, no allocation) ----------------
__device__ __align__(16) float   g_h  [N_NODES * HID];
__device__ __align__(16) __half2 g_t2h[N_NODES * HID / 2];
__device__ __align__(16) __half  g_wph[4 * 256 * 256];   // fp16 weights, k-major [m][k][n]
__device__ int g_cur[N_NODES];          // zero at module load; re-zeroed by pool tail
__device__ __align__(16) int g_ell[N_NODES * ELL_CAP];

__device__ __forceinline__ float silu(float v) {
    return v / (1.0f + expf(-v));
}

__device__ __forceinline__ int clampi(int v, int hi) {
    return v < 0 ? 0 : (v >= hi ? hi - 1 : v);
}

__device__ __forceinline__ void mma_f16(float* d, const unsigned* a, const unsigned* b) {
    asm volatile(
        "mma.sync.aligned.m16n8k16.row.col.f32.f16.f16.f32 "
        "{%0,%1,%2,%3}, {%4,%5,%6,%7}, {%8,%9}, {%0,%1,%2,%3};"
        : "+f"(d[0]), "+f"(d[1]), "+f"(d[2]), "+f"(d[3])
        : "r"(a[0]), "r"(a[1]), "r"(a[2]), "r"(a[3]),
          "r"(b[0]), "r"(b[1]));
}

__device__ __forceinline__ void ldsm_x4(unsigned* r, uint32_t addr) {
    asm volatile("ldmatrix.sync.aligned.m8n8.x4.shared.b16 {%0,%1,%2,%3}, [%4];"
                 : "=r"(r[0]), "=r"(r[1]), "=r"(r[2]), "=r"(r[3]) : "r"(addr));
}

__device__ __forceinline__ void ldsm_x4_trans(unsigned* r, uint32_t addr) {
    asm volatile("ldmatrix.sync.aligned.m8n8.x4.trans.shared.b16 {%0,%1,%2,%3}, [%4];"
                 : "=r"(r[0]), "=r"(r[1]), "=r"(r[2]), "=r"(r[3]) : "r"(addr));
}

__device__ __forceinline__ void cp16(void* smem_dst, const void* gsrc) {
    unsigned s = (unsigned)__cvta_generic_to_shared(smem_dst);
    asm volatile("cp.async.ca.shared.global [%0], [%1], 16;"
                 :: "r"(s), "l"(gsrc));
}

// --------- setup: ELL fill + W half-pack (embed fused into conv1) ----------
__global__ void setup_kernel(const int* __restrict__ src,
                             const int* __restrict__ dst,
                             const float* __restrict__ W1a,
                             const float* __restrict__ W1b,
                             const float* __restrict__ W2a,
                             const float* __restrict__ W2b) {
    int blk = blockIdx.x;
    if (blk < FILL_BLOCKS) {
        int e = blk * 256 + threadIdx.x;
        if (e < N_EDGES) {
            int d = clampi(dst[e], N_NODES);
            int slot = atomicAdd(&g_cur[d], 1);
            if (slot < ELL_CAP)
                g_ell[d * ELL_CAP + slot] = clampi(src[e], N_NODES);
        }
    } else {
        int t = (blk - FILL_BLOCKS) * 256 + threadIdx.x;  // 0..65535
        int m   = t >> 14;                 // matrix 0..3
        int off = (t & 16383) * 4;         // element offset (W is [k][n] row-major)
        const float* Wm = (m == 0) ? W1a : (m == 1) ? W1b : (m == 2) ? W2a : W2b;
        float4 v = *(const float4*)(Wm + off);
        __half2* d2 = (__half2*)(g_wph + m * 65536 + off);
        d2[0] = __floats2half2_rn(v.x, v.y);
        d2[1] = __floats2half2_rn(v.z, v.w);
    }
}

// ---------------- fused conv: t2h = (relu(h@Wa+ba))@Wb + bb -----------------
// Block: 64 rows x full 256 cols, 256 threads (8 warps; warp = 32x64, 2 mi).
// EMBED=true: A tile computed from x (IN_DIM=1) and fp32 h written to g_h.
#define FBM 64
#define FAS16 264                  // b16 per As row (256 + 8)
#define FBS16 264                  // b16 per Bs row
#define FA_B16 (FBM * FAS16)       // 16896 halves
#define FB_B16 (32 * FBS16)        // 8448 halves per buffer
#define FUSED_SMEM ((FA_B16 + 2 * FB_B16) * 2)   // 67584 bytes

// B tile kt: 32 k-rows x 256 halves; 1024 16B chunks / 256 threads
__device__ __forceinline__ void cpB(__half* dst, const __half* __restrict__ Wp,
                                    int kt, int tid) {
#pragma unroll
    for (int i = 0; i < 4; i++) {
        int l = tid + 256 * i;          // 0..1023
        int r  = l >> 5;                // k row 0..31
        int c8 = (l & 31) * 8;          // half col 0..248
        cp16(&dst[r * FBS16 + c8], Wp + (size_t)(kt * 32 + r) * 256 + c8);
    }
}

template <bool EMBED>
__global__ void __launch_bounds__(256, 2)
conv_fused(const float* __restrict__ A,        // g_h (read when !EMBED, written when EMBED)
           const float* __restrict__ x,        // node features [N,1] (EMBED only)
           const float* __restrict__ w_emb,    // [1,256] (EMBED only)
           const float* __restrict__ b_emb,    // [256]   (EMBED only)
           const __half* __restrict__ Wa, const float* __restrict__ ba,
           const __half* __restrict__ Wb, const float* __restrict__ bb,
           __half2* __restrict__ out, float* __restrict__ hOut, int M) {
    extern __shared__ __half sm16[];
    __half* As = sm16;                     // 64 x 264 (A tile, then C1)
    __half* Bs = sm16 + FA_B16;            // 2 x 32 x 264

    int tid = threadIdx.x, lane = tid & 31, w = tid >> 5;
    int wr = (w & 1) * 32;                 // warp row offset (0/32)
    int wc = (w >> 1) * 64;                // warp col offset (0/64/128/192)
    int rowBase = blockIdx.x * FBM;
    int g = lane >> 2, t4 = lane & 3;
    int lr = lane & 7, q = lane >> 3;      // ldmatrix lane groups

    uint32_t as_u = (uint32_t)__cvta_generic_to_shared(As);
    uint32_t bs_u[2];
    bs_u[0] = (uint32_t)__cvta_generic_to_shared(Bs);
    bs_u[1] = bs_u[0] + FB_B16 * 2;

    uint32_t aA0 = as_u + (uint32_t)(((wr + (q & 1) * 8 + lr) * FAS16 + (q >> 1) * 8) * 2);
    uint32_t aA1 = aA0 + 16 * FAS16 * 2;
    uint32_t bOff = (uint32_t)((((q & 1) * 8 + lr) * FBS16 + (q >> 1) * 8) * 2);

    // A tile -> half smem (64 rows x 64 float4)
#pragma unroll
    for (int i = 0; i < 16; i++) {
        int l = tid + 256 * i;
        int r = l >> 6, c4 = l & 63;
        int grow = rowBase + r;
        float4 v = make_float4(0.f, 0.f, 0.f, 0.f);
        if (EMBED) {
            if (grow < M) {
                float xv = x[grow];
                float4 we = *(const float4*)(w_emb + c4 * 4);
                float4 be = *(const float4*)(b_emb + c4 * 4);
                v.x = silu(xv * we.x + be.x);
                v.y = silu(xv * we.y + be.y);
                v.z = silu(xv * we.z + be.z);
                v.w = silu(xv * we.w + be.w);
                *(float4*)(hOut + (size_t)grow * HID + c4 * 4) = v;   // fp32 h for agg/conv2/pool
            }
        } else {
            if (grow < M) v = *(const float4*)(A + (size_t)grow * HID + c4 * 4);
        }
        __half2* row2 = (__half2*)(As + r * FAS16);
        row2[c4 * 2]     = __floats2half2_rn(v.x, v.y);
        row2[c4 * 2 + 1] = __floats2half2_rn(v.z, v.w);
    }

    float acc[2][8][4];
#pragma unroll
    for (int mi = 0; mi < 2; mi++)
#pragma unroll
        for (int ni = 0; ni < 8; ni++)
#pragma unroll
            for (int r = 0; r < 4; r++) acc[mi][ni][r] = 0.0f;

#pragma unroll
    for (int stage = 0; stage < 2; stage++) {
        const __half* Wp = (stage == 0) ? Wa : Wb;
        cpB(Bs, Wp, 0, tid);
        asm volatile("cp.async.commit_group;");
        int buf = 0;
#pragma unroll
        for (int kt = 0; kt < 8; kt++) {
            asm volatile("cp.async.wait_group 0;");
            __syncthreads();               // tile kt visible; prior reads of buf^1 done
            if (kt < 7) {
                cpB(Bs + (buf ^ 1) * FB_B16, Wp, kt + 1, tid);
                asm volatile("cp.async.commit_group;");
            }
#pragma unroll
            for (int s = 0; s < 2; s++) {
                uint32_t aoff = (uint32_t)((kt * 32 + s * 16) * 2);
                unsigned a0[4], a1[4];
                ldsm_x4(a0, aA0 + aoff);
                ldsm_x4(a1, aA1 + aoff);
                uint32_t bbase = bs_u[buf] + bOff + (uint32_t)(s * 16 * FBS16 * 2);
#pragma unroll
                for (int nj = 0; nj < 4; nj++) {
                    unsigned b[4];
                    ldsm_x4_trans(b, bbase + (uint32_t)((wc + nj * 16) * 2));
                    mma_f16(acc[0][nj * 2],     a0, b);
                    mma_f16(acc[0][nj * 2 + 1], a0, b + 2);
                    mma_f16(acc[1][nj * 2],     a1, b);
                    mma_f16(acc[1][nj * 2 + 1], a1, b + 2);
                }
            }
            buf ^= 1;
        }
        __syncthreads();                   // all stage reads done before As overwrite

        if (stage == 0) {
            // epilogue 1: C1 = relu(acc + ba) -> back into As; reset acc
#pragma unroll
            for (int mi = 0; mi < 2; mi++)
#pragma unroll
                for (int ni = 0; ni < 8; ni++) {
                    int col = wc + ni * 8 + t4 * 2;
                    float b0 = ba[col], b1 = ba[col + 1];
                    float v00 = fmaxf(acc[mi][ni][0] + b0, 0.f);
                    float v01 = fmaxf(acc[mi][ni][1] + b1, 0.f);
                    float v10 = fmaxf(acc[mi][ni][2] + b0, 0.f);
                    float v11 = fmaxf(acc[mi][ni][3] + b1, 0.f);
                    int r0 = wr + mi * 16 + g;
                    ((__half2*)(As + r0 * FAS16))[col >> 1]       = __floats2half2_rn(v00, v01);
                    ((__half2*)(As + (r0 + 8) * FAS16))[col >> 1] = __floats2half2_rn(v10, v11);
                    acc[mi][ni][0] = acc[mi][ni][1] = acc[mi][ni][2] = acc[mi][ni][3] = 0.0f;
                }
        }
    }

    // epilogue 2: out = acc + bb (half2 global store)
#pragma unroll
    for (int mi = 0; mi < 2; mi++)
#pragma unroll
        for (int ni = 0; ni < 8; ni++) {
            int col = wc + ni * 8 + t4 * 2;
            float b0 = bb[col], b1 = bb[col + 1];
            int r0 = rowBase + wr + mi * 16 + g;
            int r1 = r0 + 8;
            if (r0 < M)
                out[(size_t)r0 * (HID / 2) + (col >> 1)] =
                    __floats2half2_rn(acc[mi][ni][0] + b0, acc[mi][ni][1] + b1);
            if (r1 < M)
                out[(size_t)r1 * (HID / 2) + (col >> 1)] =
                    __floats2half2_rn(acc[mi][ni][2] + b0, acc[mi][ni][3] + b1);
        }
}

// ------- edge aggregation: warp-per-node float4 gather-max (R7 2-deep) ------
__global__ void agg_kernel() {
    const unsigned FULL = 0xffffffffu;
    int warp = threadIdx.x >> 5;
    int lane = threadIdx.x & 31;
    int n = blockIdx.x * 8 + warp;
    if (n >= N_NODES) return;

    int cnt = min(g_cur[n], ELL_CAP);
    const int* lst = g_ell + n * ELL_CAP;
    const float4* t2v = (const float4*)g_t2h;   // 32 float4 per row

    unsigned ninf = 0xFC00FC00u;
    __half2 mneg = *(__half2*)&ninf;
    __half2 m[8];
#pragma unroll
    for (int q = 0; q < 8; q++) m[q] = mneg;

    for (int base = 0; base < cnt; base += 32) {
        int e = base + lane;
        int idx = (e < cnt) ? lst[e] : 0;
        int c = min(32, cnt - base);
        int j = 0;
        for (; j + 2 <= c; j += 2) {
            int s0 = __shfl_sync(FULL, idx, j);
            int s1 = __shfl_sync(FULL, idx, j + 1);
            float4 v0 = t2v[s0 * 32 + lane];
            float4 v1 = t2v[s1 * 32 + lane];
            m[0] = __hmax2(m[0], *(__half2*)&v0.x);
            m[1] = __hmax2(m[1], *(__half2*)&v0.y);
            m[2] = __hmax2(m[2], *(__half2*)&v0.z);
            m[3] = __hmax2(m[3], *(__half2*)&v0.w);
            m[4] = __hmax2(m[4], *(__half2*)&v1.x);
            m[5] = __hmax2(m[5], *(__half2*)&v1.y);
            m[6] = __hmax2(m[6], *(__half2*)&v1.z);
            m[7] = __hmax2(m[7], *(__half2*)&v1.w);
        }
        if (j < c) {
            int s0 = __shfl_sync(FULL, idx, j);
            float4 v0 = t2v[s0 * 32 + lane];
            m[0] = __hmax2(m[0], *(__half2*)&v0.x);
            m[1] = __hmax2(m[1], *(__half2*)&v0.y);
            m[2] = __hmax2(m[2], *(__half2*)&v0.z);
            m[3] = __hmax2(m[3], *(__half2*)&v0.w);
        }
    }
#pragma unroll
    for (int q = 0; q < 4; q++) m[q] = __hmax2(m[q], m[q + 4]);

    float f[8];
#pragma unroll
    for (int q = 0; q < 4; q++) {
        float2 p = __half22float2(m[q]);
        f[2 * q]     = (cnt > 0) ? p.x : 0.0f;
        f[2 * q + 1] = (cnt > 0) ? p.y : 0.0f;
    }
    float4* hp = (float4*)(g_h + (size_t)n * HID) + lane * 2;
    float4 h0 = hp[0], h1 = hp[1];
    h0.x += silu(f[0]); h0.y += silu(f[1]); h0.z += silu(f[2]); h0.w += silu(f[3]);
    h1.x += silu(f[4]); h1.y += silu(f[5]); h1.z += silu(f[6]); h1.w += silu(f[7]);
    hp[0] = h0; hp[1] = h1;
}

// ------- global mean pool (batch sorted) + re-zero g_cur for next call -----
__global__ void pool_kernel(const int* __restrict__ batch,
                            float* __restrict__ out) {
    int g = blockIdx.x;          // 0..63
    int tid = threadIdx.x;       // 0..255 feature

    int lo = 0, hi = N_NODES;
    while (lo < hi) { int m = (lo + hi) >> 1; if (batch[m] < g) lo = m + 1; else hi = m; }
    int start = lo;
    lo = start; hi = N_NODES;
    while (lo < hi) { int m = (lo + hi) >> 1; if (batch[m] < g + 1) lo = m + 1; else hi = m; }
    int end = lo;

    float s = 0.0f;
    for (int n = start; n < end; n++)
        s += g_h[(size_t)n * HID + tid];
    float c = (float)(end - start);
    out[g * HID + tid] = s / fmaxf(c, 1.0f);

    int z = g * 256 + tid;       // 64*256 = 16384 >= N_NODES
    if (z < N_NODES) g_cur[z] = 0;
}

// ---------------- launch ----------------
extern "C" void kernel_launch(void* const* d_in, const int* in_sizes, int n_in,
                              void* d_out, int out_size) {
    const float* x     = (const float*)d_in[0];
    const int*   ei    = (const int*)d_in[1];
    const int*   batch = (const int*)d_in[2];
    const float* W_emb = (const float*)d_in[3];
    const float* b_emb = (const float*)d_in[4];
    const float* W1a   = (const float*)d_in[5];
    const float* b1a   = (const float*)d_in[6];
    const float* W1b   = (const float*)d_in[7];
    const float* b1b   = (const float*)d_in[8];
    const float* W2a   = (const float*)d_in[9];
    const float* b2a   = (const float*)d_in[10];
    const float* W2b   = (const float*)d_in[11];
    const float* b2b   = (const float*)d_in[12];
    float* out = (float*)d_out;

    const int* src = ei;
    const int* dst = ei + N_EDGES;

    float* h = nullptr; __half2* t2h = nullptr; __half* wph = nullptr;
    cudaGetSymbolAddress((void**)&h,   g_h);
    cudaGetSymbolAddress((void**)&t2h, g_t2h);
    cudaGetSymbolAddress((void**)&wph, g_wph);

    cudaFuncSetAttribute((const void*)conv_fused<true>,
        cudaFuncAttributeMaxDynamicSharedMemorySize, FUSED_SMEM);
    cudaFuncSetAttribute((const void*)conv_fused<false>,
        cudaFuncAttributeMaxDynamicSharedMemorySize, FUSED_SMEM);

    // setup: ELL fill + W pack (embed now fused into conv1)
    setup_kernel<<<FILL_BLOCKS + PACK_BLOCKS, 256>>>(src, dst, W1a, W1b, W2a, W2b);

    int fgrid = (N_NODES + FBM - 1) / FBM;   // 157

    // conv 1 (embed + fused MLP) + aggregation
    conv_fused<true><<<fgrid, 256, FUSED_SMEM>>>(
        nullptr, x, W_emb, b_emb, wph, b1a, wph + 65536, b1b, t2h, h, N_NODES);
    agg_kernel<<<1250, 256>>>();

    // conv 2 (reads h updated by agg 1)
    conv_fused<false><<<fgrid, 256, FUSED_SMEM>>>(
        h, nullptr, nullptr, nullptr, wph + 131072, b2a, wph + 196608, b2b, t2h, nullptr, N_NODES);
    agg_kernel<<<1250, 256>>>();

    // conv 2's aggregation feeds h; global mean pool (+ g_cur re-zero)
    pool_kernel<<<N_GRAPHS, 256>>>(batch, out);
}

// round 17
// speedup vs baseline: 1.1247x; 1.0974x over previous
#include <cuda_runtime.h>
#include <cuda_fp16.h>
#include <cstdint>
#include <math.h>

#define N_NODES 10000
#define N_EDGES 320000
#define N_GRAPHS 64
#define HID 256
#define ELL_CAP 128
#define FILL_BLOCKS 1250           // 1250*256 = 320000 edges
#define PACK_BLOCKS 256            // 4 matrices * 65536 halves / (256 thr * 4)

// ---------------- scratch (static __device__, no allocation) ----------------
__device__ __align__(16) float   g_h  [N_NODES * HID];
__device__ __align__(16) __half2 g_t2h[N_NODES * HID / 2];
__device__ __align__(16) __half  g_wph[4 * 256 * 256];   // fp16 weights, k-major [m][k][n]
__device__ int g_cur[N_NODES];          // zero at module load; re-zeroed by pool tail
__device__ __align__(16) int g_ell[N_NODES * ELL_CAP];

__device__ __forceinline__ float silu(float v) {
    return v / (1.0f + expf(-v));
}

__device__ __forceinline__ int clampi(int v, int hi) {
    return v < 0 ? 0 : (v >= hi ? hi - 1 : v);
}

__device__ __forceinline__ void mma_f16(float* d, const unsigned* a, const unsigned* b) {
    asm volatile(
        "mma.sync.aligned.m16n8k16.row.col.f32.f16.f16.f32 "
        "{%0,%1,%2,%3}, {%4,%5,%6,%7}, {%8,%9}, {%0,%1,%2,%3};"
        : "+f"(d[0]), "+f"(d[1]), "+f"(d[2]), "+f"(d[3])
        : "r"(a[0]), "r"(a[1]), "r"(a[2]), "r"(a[3]),
          "r"(b[0]), "r"(b[1]));
}

__device__ __forceinline__ void ldsm_x4(unsigned* r, uint32_t addr) {
    asm volatile("ldmatrix.sync.aligned.m8n8.x4.shared.b16 {%0,%1,%2,%3}, [%4];"
                 : "=r"(r[0]), "=r"(r[1]), "=r"(r[2]), "=r"(r[3]) : "r"(addr));
}

__device__ __forceinline__ void ldsm_x4_trans(unsigned* r, uint32_t addr) {
    asm volatile("ldmatrix.sync.aligned.m8n8.x4.trans.shared.b16 {%0,%1,%2,%3}, [%4];"
                 : "=r"(r[0]), "=r"(r[1]), "=r"(r[2]), "=r"(r[3]) : "r"(addr));
}

__device__ __forceinline__ void cp16(void* smem_dst, const void* gsrc) {
    unsigned s = (unsigned)__cvta_generic_to_shared(smem_dst);
    asm volatile("cp.async.ca.shared.global [%0], [%1], 16;"
                 :: "r"(s), "l"(gsrc));
}

// --------- setup: W half-pack only (fill fused into conv1, embed too) -------
__global__ void setup_kernel(const float* __restrict__ W1a,
                             const float* __restrict__ W1b,
                             const float* __restrict__ W2a,
                             const float* __restrict__ W2b) {
    int t = blockIdx.x * 256 + threadIdx.x;   // 0..65535
    int m   = t >> 14;                 // matrix 0..3
    int off = (t & 16383) * 4;         // element offset (W is [k][n] row-major)
    const float* Wm = (m == 0) ? W1a : (m == 1) ? W1b : (m == 2) ? W2a : W2b;
    float4 v = *(const float4*)(Wm + off);
    __half2* d2 = (__half2*)(g_wph + m * 65536 + off);
    d2[0] = __floats2half2_rn(v.x, v.y);
    d2[1] = __floats2half2_rn(v.z, v.w);
}

// ---------------- fused conv: t2h = (relu(h@Wa+ba))@Wb + bb -----------------
// Block: 64 rows x full 256 cols, 256 threads (8 warps; warp = 32x64, 2 mi).
// EMBED=true: A tile computed from x (IN_DIM=1), fp32 h written to g_h, and
// blocks [convBlocks, convBlocks+FILL_BLOCKS) do the ELL fill (overlapped).
#define FBM 64
#define FAS16 264                  // b16 per As row (256 + 8)
#define FBS16 264                  // b16 per Bs row
#define FA_B16 (FBM * FAS16)       // 16896 halves
#define FB_B16 (32 * FBS16)        // 8448 halves per buffer
#define FUSED_SMEM ((FA_B16 + 2 * FB_B16) * 2)   // 67584 bytes

// B tile kt: 32 k-rows x 256 halves; 1024 16B chunks / 256 threads
__device__ __forceinline__ void cpB(__half* dst, const __half* __restrict__ Wp,
                                    int kt, int tid) {
#pragma unroll
    for (int i = 0; i < 4; i++) {
        int l = tid + 256 * i;          // 0..1023
        int r  = l >> 5;                // k row 0..31
        int c8 = (l & 31) * 8;          // half col 0..248
        cp16(&dst[r * FBS16 + c8], Wp + (size_t)(kt * 32 + r) * 256 + c8);
    }
}

template <bool EMBED>
__global__ void __launch_bounds__(256, 2)
conv_fused(const float* __restrict__ A,        // g_h (read when !EMBED)
           const float* __restrict__ x,        // node features [N,1] (EMBED only)
           const float* __restrict__ w_emb,    // [1,256] (EMBED only)
           const float* __restrict__ b_emb,    // [256]   (EMBED only)
           const int* __restrict__ src,        // edge src (EMBED only, fill blocks)
           const int* __restrict__ dst,        // edge dst (EMBED only, fill blocks)
           const __half* __restrict__ Wa, const float* __restrict__ ba,
           const __half* __restrict__ Wb, const float* __restrict__ bb,
           __half2* __restrict__ out, float* __restrict__ hOut,
           int convBlocks, int M) {
    int tid = threadIdx.x;

    if (EMBED && blockIdx.x >= convBlocks) {
        // ---- ELL fill block (overlaps with conv compute; consumed by agg) ----
        int e = (blockIdx.x - convBlocks) * 256 + tid;
        if (e < N_EDGES) {
            int d = clampi(dst[e], N_NODES);
            int slot = atomicAdd(&g_cur[d], 1);
            if (slot < ELL_CAP)
                g_ell[d * ELL_CAP + slot] = clampi(src[e], N_NODES);
        }
        return;
    }

    extern __shared__ __half sm16[];
    __half* As = sm16;                     // 64 x 264 (A tile, then C1)
    __half* Bs = sm16 + FA_B16;            // 2 x 32 x 264

    int lane = tid & 31, w = tid >> 5;
    int wr = (w & 1) * 32;                 // warp row offset (0/32)
    int wc = (w >> 1) * 64;                // warp col offset (0/64/128/192)
    int rowBase = blockIdx.x * FBM;
    int g = lane >> 2, t4 = lane & 3;
    int lr = lane & 7, q = lane >> 3;      // ldmatrix lane groups

    uint32_t as_u = (uint32_t)__cvta_generic_to_shared(As);
    uint32_t bs_u[2];
    bs_u[0] = (uint32_t)__cvta_generic_to_shared(Bs);
    bs_u[1] = bs_u[0] + FB_B16 * 2;

    uint32_t aA0 = as_u + (uint32_t)(((wr + (q & 1) * 8 + lr) * FAS16 + (q >> 1) * 8) * 2);
    uint32_t aA1 = aA0 + 16 * FAS16 * 2;
    uint32_t bOff = (uint32_t)((((q & 1) * 8 + lr) * FBS16 + (q >> 1) * 8) * 2);

    // A tile -> half smem (64 rows x 64 float4)
#pragma unroll
    for (int i = 0; i < 16; i++) {
        int l = tid + 256 * i;
        int r = l >> 6, c4 = l & 63;
        int grow = rowBase + r;
        float4 v = make_float4(0.f, 0.f, 0.f, 0.f);
        if (EMBED) {
            if (grow < M) {
                float xv = x[grow];
                float4 we = *(const float4*)(w_emb + c4 * 4);
                float4 be = *(const float4*)(b_emb + c4 * 4);
                v.x = silu(xv * we.x + be.x);
                v.y = silu(xv * we.y + be.y);
                v.z = silu(xv * we.z + be.z);
                v.w = silu(xv * we.w + be.w);
                *(float4*)(hOut + (size_t)grow * HID + c4 * 4) = v;   // fp32 h for agg/conv2/pool
            }
        } else {
            if (grow < M) v = *(const float4*)(A + (size_t)grow * HID + c4 * 4);
        }
        __half2* row2 = (__half2*)(As + r * FAS16);
        row2[c4 * 2]     = __floats2half2_rn(v.x, v.y);
        row2[c4 * 2 + 1] = __floats2half2_rn(v.z, v.w);
    }

    float acc[2][8][4];
#pragma unroll
    for (int mi = 0; mi < 2; mi++)
#pragma unroll
        for (int ni = 0; ni < 8; ni++)
#pragma unroll
            for (int r = 0; r < 4; r++) acc[mi][ni][r] = 0.0f;

#pragma unroll
    for (int stage = 0; stage < 2; stage++) {
        const __half* Wp = (stage == 0) ? Wa : Wb;
        cpB(Bs, Wp, 0, tid);
        asm volatile("cp.async.commit_group;");
        int buf = 0;
#pragma unroll
        for (int kt = 0; kt < 8; kt++) {
            asm volatile("cp.async.wait_group 0;");
            __syncthreads();               // tile kt visible; prior reads of buf^1 done
            if (kt < 7) {
                cpB(Bs + (buf ^ 1) * FB_B16, Wp, kt + 1, tid);
                asm volatile("cp.async.commit_group;");
            }
#pragma unroll
            for (int s = 0; s < 2; s++) {
                uint32_t aoff = (uint32_t)((kt * 32 + s * 16) * 2);
                unsigned a0[4], a1[4];
                ldsm_x4(a0, aA0 + aoff);
                ldsm_x4(a1, aA1 + aoff);
                uint32_t bbase = bs_u[buf] + bOff + (uint32_t)(s * 16 * FBS16 * 2);
#pragma unroll
                for (int nj = 0; nj < 4; nj++) {
                    unsigned b[4];
                    ldsm_x4_trans(b, bbase + (uint32_t)((wc + nj * 16) * 2));
                    mma_f16(acc[0][nj * 2],     a0, b);
                    mma_f16(acc[0][nj * 2 + 1], a0, b + 2);
                    mma_f16(acc[1][nj * 2],     a1, b);
                    mma_f16(acc[1][nj * 2 + 1], a1, b + 2);
                }
            }
            buf ^= 1;
        }
        __syncthreads();                   // all stage reads done before As overwrite

        if (stage == 0) {
            // epilogue 1: C1 = relu(acc + ba) -> back into As; reset acc
#pragma unroll
            for (int mi = 0; mi < 2; mi++)
#pragma unroll
                for (int ni = 0; ni < 8; ni++) {
                    int col = wc + ni * 8 + t4 * 2;
                    float b0 = ba[col], b1 = ba[col + 1];
                    float v00 = fmaxf(acc[mi][ni][0] + b0, 0.f);
                    float v01 = fmaxf(acc[mi][ni][1] + b1, 0.f);
                    float v10 = fmaxf(acc[mi][ni][2] + b0, 0.f);
                    float v11 = fmaxf(acc[mi][ni][3] + b1, 0.f);
                    int r0 = wr + mi * 16 + g;
                    ((__half2*)(As + r0 * FAS16))[col >> 1]       = __floats2half2_rn(v00, v01);
                    ((__half2*)(As + (r0 + 8) * FAS16))[col >> 1] = __floats2half2_rn(v10, v11);
                    acc[mi][ni][0] = acc[mi][ni][1] = acc[mi][ni][2] = acc[mi][ni][3] = 0.0f;
                }
        }
    }

    // epilogue 2: out = acc + bb (half2 global store)
#pragma unroll
    for (int mi = 0; mi < 2; mi++)
#pragma unroll
        for (int ni = 0; ni < 8; ni++) {
            int col = wc + ni * 8 + t4 * 2;
            float b0 = bb[col], b1 = bb[col + 1];
            int r0 = rowBase + wr + mi * 16 + g;
            int r1 = r0 + 8;
            if (r0 < M)
                out[(size_t)r0 * (HID / 2) + (col >> 1)] =
                    __floats2half2_rn(acc[mi][ni][0] + b0, acc[mi][ni][1] + b1);
            if (r1 < M)
                out[(size_t)r1 * (HID / 2) + (col >> 1)] =
                    __floats2half2_rn(acc[mi][ni][2] + b0, acc[mi][ni][3] + b1);
        }
}

// ------- edge aggregation: warp-per-node float4 gather-max (R7 2-deep) ------
__global__ void agg_kernel() {
    const unsigned FULL = 0xffffffffu;
    int warp = threadIdx.x >> 5;
    int lane = threadIdx.x & 31;
    int n = blockIdx.x * 8 + warp;
    if (n >= N_NODES) return;

    int cnt = min(g_cur[n], ELL_CAP);
    const int* lst = g_ell + n * ELL_CAP;
    const float4* t2v = (const float4*)g_t2h;   // 32 float4 per row

    unsigned ninf = 0xFC00FC00u;
    __half2 mneg = *(__half2*)&ninf;
    __half2 m[8];
#pragma unroll
    for (int q = 0; q < 8; q++) m[q] = mneg;

    for (int base = 0; base < cnt; base += 32) {
        int e = base + lane;
        int idx = (e < cnt) ? lst[e] : 0;
        int c = min(32, cnt - base);
        int j = 0;
        for (; j + 2 <= c; j += 2) {
            int s0 = __shfl_sync(FULL, idx, j);
            int s1 = __shfl_sync(FULL, idx, j + 1);
            float4 v0 = t2v[s0 * 32 + lane];
            float4 v1 = t2v[s1 * 32 + lane];
            m[0] = __hmax2(m[0], *(__half2*)&v0.x);
            m[1] = __hmax2(m[1], *(__half2*)&v0.y);
            m[2] = __hmax2(m[2], *(__half2*)&v0.z);
            m[3] = __hmax2(m[3], *(__half2*)&v0.w);
            m[4] = __hmax2(m[4], *(__half2*)&v1.x);
            m[5] = __hmax2(m[5], *(__half2*)&v1.y);
            m[6] = __hmax2(m[6], *(__half2*)&v1.z);
            m[7] = __hmax2(m[7], *(__half2*)&v1.w);
        }
        if (j < c) {
            int s0 = __shfl_sync(FULL, idx, j);
            float4 v0 = t2v[s0 * 32 + lane];
            m[0] = __hmax2(m[0], *(__half2*)&v0.x);
            m[1] = __hmax2(m[1], *(__half2*)&v0.y);
            m[2] = __hmax2(m[2], *(__half2*)&v0.z);
            m[3] = __hmax2(m[3], *(__half2*)&v0.w);
        }
    }
#pragma unroll
    for (int q = 0; q < 4; q++) m[q] = __hmax2(m[q], m[q + 4]);

    float f[8];
#pragma unroll
    for (int q = 0; q < 4; q++) {
        float2 p = __half22float2(m[q]);
        f[2 * q]     = (cnt > 0) ? p.x : 0.0f;
        f[2 * q + 1] = (cnt > 0) ? p.y : 0.0f;
    }
    float4* hp = (float4*)(g_h + (size_t)n * HID) + lane * 2;
    float4 h0 = hp[0], h1 = hp[1];
    h0.x += silu(f[0]); h0.y += silu(f[1]); h0.z += silu(f[2]); h0.w += silu(f[3]);
    h1.x += silu(f[4]); h1.y += silu(f[5]); h1.z += silu(f[6]); h1.w += silu(f[7]);
    hp[0] = h0; hp[1] = h1;
}

// ------- global mean pool (batch sorted) + re-zero g_cur for next call -----
__global__ void pool_kernel(const int* __restrict__ batch,
                            float* __restrict__ out) {
    int g = blockIdx.x;          // 0..63
    int tid = threadIdx.x;       // 0..255 feature

    int lo = 0, hi = N_NODES;
    while (lo < hi) { int m = (lo + hi) >> 1; if (batch[m] < g) lo = m + 1; else hi = m; }
    int start = lo;
    lo = start; hi = N_NODES;
    while (lo < hi) { int m = (lo + hi) >> 1; if (batch[m] < g + 1) lo = m + 1; else hi = m; }
    int end = lo;

    float s = 0.0f;
    for (int n = start; n < end; n++)
        s += g_h[(size_t)n * HID + tid];
    float c = (float)(end - start);
    out[g * HID + tid] = s / fmaxf(c, 1.0f);

    int z = g * 256 + tid;       // 64*256 = 16384 >= N_NODES
    if (z < N_NODES) g_cur[z] = 0;
}

// ---------------- launch ----------------
extern "C" void kernel_launch(void* const* d_in, const int* in_sizes, int n_in,
                              void* d_out, int out_size) {
    const float* x     = (const float*)d_in[0];
    const int*   ei    = (const int*)d_in[1];
    const int*   batch = (const int*)d_in[2];
    const float* W_emb = (const float*)d_in[3];
    const float* b_emb = (const float*)d_in[4];
    const float* W1a   = (const float*)d_in[5];
    const float* b1a   = (const float*)d_in[6];
    const float* W1b   = (const float*)d_in[7];
    const float* b1b   = (const float*)d_in[8];
    const float* W2a   = (const float*)d_in[9];
    const float* b2a   = (const float*)d_in[10];
    const float* W2b   = (const float*)d_in[11];
    const float* b2b   = (const float*)d_in[12];
    float* out = (float*)d_out;

    const int* src = ei;
    const int* dst = ei + N_EDGES;

    float* h = nullptr; __half2* t2h = nullptr; __half* wph = nullptr;
    cudaGetSymbolAddress((void**)&h,   g_h);
    cudaGetSymbolAddress((void**)&t2h, g_t2h);
    cudaGetSymbolAddress((void**)&wph, g_wph);

    cudaFuncSetAttribute((const void*)conv_fused<true>,
        cudaFuncAttributeMaxDynamicSharedMemorySize, FUSED_SMEM);
    cudaFuncSetAttribute((const void*)conv_fused<false>,
        cudaFuncAttributeMaxDynamicSharedMemorySize, FUSED_SMEM);

    // setup: W pack only (~2 us)
    setup_kernel<<<PACK_BLOCKS, 256>>>(W1a, W1b, W2a, W2b);

    int fgrid = (N_NODES + FBM - 1) / FBM;   // 157

    // conv 1 (embed + fused MLP + overlapped ELL fill) + aggregation
    conv_fused<true><<<fgrid + FILL_BLOCKS, 256, FUSED_SMEM>>>(
        nullptr, x, W_emb, b_emb, src, dst,
        wph, b1a, wph + 65536, b1b, t2h, h, fgrid, N_NODES);
    agg_kernel<<<1250, 256>>>();

    // conv 2 (reads h updated by agg 1)
    conv_fused<false><<<fgrid, 256, FUSED_SMEM>>>(
        h, nullptr, nullptr, nullptr, nullptr, nullptr,
        wph + 131072, b2a, wph + 196608, b2b, t2h, nullptr, fgrid, N_NODES);
    agg_kernel<<<1250, 256>>>();

    // global mean pool (+ g_cur re-zero)
    pool_kernel<<<N_GRAPHS, 256>>>(batch, out);
}